// round 4
// baseline (speedup 1.0000x reference)
#include <cuda_runtime.h>
#include <cstdint>

#define Bdim 8
#define Tdim 2048
#define Cdim 1024
#define Hdim 128
#define BT (Bdim*Tdim)

// Scratch (device globals, allocation-free).
__device__ float g_Q[BT * Hdim];   // pre-scaled, tf32-rounded
__device__ float g_K[BT * Hdim];   // tf32-rounded
__device__ float g_V[BT * Hdim];   // tf32-rounded
__device__ float g_Op[2 * BT * Hdim];  // unnormalized partial O per half
__device__ float g_m[2 * BT];          // row max per half
__device__ float g_l[2 * BT];          // row sum per half

// ---------------------------------------------------------------------------
// Helpers
// ---------------------------------------------------------------------------
__device__ __forceinline__ uint32_t cvt_tf32(float x) {
    uint32_t u;
    asm("cvt.rna.tf32.f32 %0, %1;" : "=r"(u) : "f"(x));
    return u;
}
__device__ __forceinline__ float cvt_tf32f(float x) {
    return __uint_as_float(cvt_tf32(x));
}
__device__ __forceinline__ void mma_tf32(float* d, const uint32_t* a,
                                         uint32_t b0, uint32_t b1) {
    asm volatile(
        "mma.sync.aligned.m16n8k8.row.col.f32.tf32.tf32.f32 "
        "{%0,%1,%2,%3}, {%4,%5,%6,%7}, {%8,%9}, {%0,%1,%2,%3};"
        : "+f"(d[0]), "+f"(d[1]), "+f"(d[2]), "+f"(d[3])
        : "r"(a[0]), "r"(a[1]), "r"(a[2]), "r"(a[3]), "r"(b0), "r"(b1));
}
__device__ __forceinline__ uint32_t s2u(const void* p) {
    return (uint32_t)__cvta_generic_to_shared(p);
}
__device__ __forceinline__ void cpa16(uint32_t dst, const void* src) {
    asm volatile("cp.async.cg.shared.global [%0], [%1], 16;" :: "r"(dst), "l"(src));
}
__device__ __forceinline__ void cpa_commit() {
    asm volatile("cp.async.commit_group;");
}
__device__ __forceinline__ void cpa_wait0() {
    asm volatile("cp.async.wait_group 0;");
}

// ---------------------------------------------------------------------------
// Kernel 1: fused QKV projection (x read ONCE), TF32 MMA, double-buffered.
// grid = 128, block = 384 (12 warps). Warp w: output o=w/4, rows (w%4)*32.
// Smem: A[2][128][36], B[2][32][396] (three 132-wide segments).
// ---------------------------------------------------------------------------
#define APAD 36
#define BROW 396   // 3 * 132
#define BSEG 132

__global__ __launch_bounds__(384, 1) void qkv_kernel(
    const float* __restrict__ x, const float* __restrict__ Wq,
    const float* __restrict__ Wk, const float* __restrict__ Wv)
{
    extern __shared__ float sm[];
    float* As[2] = { sm,              sm + 128 * APAD };
    float* Bs[2] = { sm + 2*128*APAD, sm + 2*128*APAD + 32 * BROW };

    const int m0 = blockIdx.x * 128;
    const int tid  = threadIdx.x;
    const int wid  = tid >> 5;
    const int lane = tid & 31;
    const int g    = lane >> 2;
    const int tg   = lane & 3;
    const int o    = wid >> 2;         // 0..2 (Q/K/V)
    const int wr   = (wid & 3) * 32;   // warp row base

    const float* Ws[3] = { Wq, Wk, Wv };

    // Stage chunk 0.
    {
        uint32_t au = s2u(As[0]), bu = s2u(Bs[0]);
        #pragma unroll
        for (int tt = 0; tt < 3; tt++) {
            int idx = tt * 384 + tid;
            if (idx < 1024) {
                int row = idx >> 3, c4 = idx & 7;
                cpa16(au + (row * APAD + c4 * 4) * 4,
                      x + (size_t)(m0 + row) * Cdim + c4 * 4);
            }
        }
        #pragma unroll
        for (int tt = 0; tt < 8; tt++) {
            int idx = tt * 384 + tid;
            int oo = idx >> 10, rem = idx & 1023;
            int row = rem >> 5, c4 = rem & 31;
            cpa16(bu + (row * BROW + oo * BSEG + c4 * 4) * 4,
                  Ws[oo] + (size_t)row * Hdim + c4 * 4);
        }
        cpa_commit();
    }

    float oc[2][16][4];
    #pragma unroll
    for (int mb = 0; mb < 2; mb++)
        #pragma unroll
        for (int nb = 0; nb < 16; nb++)
            #pragma unroll
            for (int c = 0; c < 4; c++) oc[mb][nb][c] = 0.f;

    #pragma unroll 1
    for (int kc = 0; kc < 32; kc++) {
        cpa_wait0();
        __syncthreads();
        const int cur = kc & 1;
        if (kc + 1 < 32) {
            const int k0 = (kc + 1) * 32;
            uint32_t au = s2u(As[cur ^ 1]), bu = s2u(Bs[cur ^ 1]);
            #pragma unroll
            for (int tt = 0; tt < 3; tt++) {
                int idx = tt * 384 + tid;
                if (idx < 1024) {
                    int row = idx >> 3, c4 = idx & 7;
                    cpa16(au + (row * APAD + c4 * 4) * 4,
                          x + (size_t)(m0 + row) * Cdim + k0 + c4 * 4);
                }
            }
            #pragma unroll
            for (int tt = 0; tt < 8; tt++) {
                int idx = tt * 384 + tid;
                int oo = idx >> 10, rem = idx & 1023;
                int row = rem >> 5, c4 = rem & 31;
                cpa16(bu + (row * BROW + oo * BSEG + c4 * 4) * 4,
                      Ws[oo] + (size_t)(k0 + row) * Hdim + c4 * 4);
            }
            cpa_commit();
        }

        const float* A = As[cur];
        const float* B = Bs[cur] + o * BSEG;
        #pragma unroll
        for (int ks = 0; ks < 4; ks++) {
            const int k = ks * 8;
            const int r0 = wr + g;
            uint32_t a0[4], a1[4];
            a0[0] = cvt_tf32(A[(r0     ) * APAD + k + tg    ]);
            a0[1] = cvt_tf32(A[(r0 +  8) * APAD + k + tg    ]);
            a0[2] = cvt_tf32(A[(r0     ) * APAD + k + tg + 4]);
            a0[3] = cvt_tf32(A[(r0 +  8) * APAD + k + tg + 4]);
            a1[0] = cvt_tf32(A[(r0 + 16) * APAD + k + tg    ]);
            a1[1] = cvt_tf32(A[(r0 + 24) * APAD + k + tg    ]);
            a1[2] = cvt_tf32(A[(r0 + 16) * APAD + k + tg + 4]);
            a1[3] = cvt_tf32(A[(r0 + 24) * APAD + k + tg + 4]);
            #pragma unroll
            for (int nb = 0; nb < 16; nb++) {
                uint32_t b0 = cvt_tf32(B[(k + tg    ) * BROW + nb * 8 + g]);
                uint32_t b1 = cvt_tf32(B[(k + tg + 4) * BROW + nb * 8 + g]);
                mma_tf32(oc[0][nb], a0, b0, b1);
                mma_tf32(oc[1][nb], a1, b0, b1);
            }
        }
    }

    float* outp = (o == 0) ? g_Q : (o == 1) ? g_K : g_V;
    const float osc = (o == 0) ? 0.08838834764831845f : 1.f;
    #pragma unroll
    for (int mb = 0; mb < 2; mb++) {
        int r0 = m0 + wr + mb * 16 + g;
        #pragma unroll
        for (int nb = 0; nb < 16; nb++) {
            float2 lo = {cvt_tf32f(oc[mb][nb][0] * osc), cvt_tf32f(oc[mb][nb][1] * osc)};
            float2 hi = {cvt_tf32f(oc[mb][nb][2] * osc), cvt_tf32f(oc[mb][nb][3] * osc)};
            *(float2*)(outp + (size_t)(r0    ) * Hdim + nb * 8 + 2 * tg) = lo;
            *(float2*)(outp + (size_t)(r0 + 8) * Hdim + nb * 8 + 2 * tg) = hi;
        }
    }
}

// ---------------------------------------------------------------------------
// Kernel 2: causal flash attention, split-KV (2 halves) + q-tile pairing.
// grid = (32, 8): blockIdx.x = (pair p)*2 + half h; blockIdx.y = batch.
// Phases: qt = p, then qt = 31-p. Half h takes kv-tiles (32-wide) of parity h
// -> exactly qt+1 tiles per phase, 33 uniform steps per CTA.
// block = 128 (4 warps, warp owns 16 q-rows). Writes unnormalized partials.
// Smem = 110.6 KB -> 2 CTAs/SM.
// ---------------------------------------------------------------------------
#define QP 132
#define KP 132
#define VP 132
#define PP 36

__global__ __launch_bounds__(128) void attn_kernel()
{
    extern __shared__ float smem[];
    float* Qs    = smem;                 // [64][132]
    float* Kb[2] = { smem +  8448, smem + 12672 };  // [32][132] x2
    float* Vb[2] = { smem + 16896, smem + 21120 };  // [32][132] x2
    float* Ps    = smem + 25344;         // [64][36]

    const int p = (int)blockIdx.x >> 1;
    const int h = (int)blockIdx.x & 1;
    const int b = blockIdx.y;
    const int tid  = threadIdx.x;
    const int wid  = tid >> 5;
    const int lane = tid & 31;
    const int g    = lane >> 2;
    const int tg   = lane & 3;
    const int r0q  = wid * 16 + g;

    const float* Q = g_Q + (size_t)b * Tdim * Hdim;
    const float* K = g_K + (size_t)b * Tdim * Hdim;
    const float* V = g_V + (size_t)b * Tdim * Hdim;

    #pragma unroll 1
    for (int phase = 0; phase < 2; phase++) {
        const int qt = phase == 0 ? p : 31 - p;
        const int m0 = qt * 64;

        __syncthreads();  // previous phase's smem fully consumed

        // Stage Q (64x128) + first K/V tile (32x128 each).
        {
            uint32_t qu = s2u(Qs);
            #pragma unroll
            for (int tt = 0; tt < 16; tt++) {
                int idx = tt * 128 + tid;
                int row = idx >> 5, c4 = idx & 31;
                cpa16(qu + (row * QP + c4 * 4) * 4,
                      Q + (size_t)(m0 + row) * Hdim + c4 * 4);
            }
            const int n0 = 32 * h;
            uint32_t ku = s2u(Kb[0]), vu = s2u(Vb[0]);
            #pragma unroll
            for (int tt = 0; tt < 8; tt++) {
                int idx = tt * 128 + tid;
                int row = idx >> 5, c4 = idx & 31;
                cpa16(ku + (row * KP + c4 * 4) * 4,
                      K + (size_t)(n0 + row) * Hdim + c4 * 4);
                cpa16(vu + (row * VP + c4 * 4) * 4,
                      V + (size_t)(n0 + row) * Hdim + c4 * 4);
            }
            cpa_commit();
        }

        float of[16][4];
        #pragma unroll
        for (int nb = 0; nb < 16; nb++)
            #pragma unroll
            for (int c = 0; c < 4; c++) of[nb][c] = 0.f;
        float mrow0 = -1e30f, mrow1 = -1e30f, lrow0 = 0.f, lrow1 = 0.f;

        #pragma unroll 1
        for (int i = 0; i <= qt; i++) {
            const int cur = i & 1;
            cpa_wait0();
            __syncthreads();

            if (i < qt) {
                const int n0n = 32 * (2 * (i + 1) + h);
                uint32_t ku = s2u(Kb[cur ^ 1]), vu = s2u(Vb[cur ^ 1]);
                #pragma unroll
                for (int tt = 0; tt < 8; tt++) {
                    int idx = tt * 128 + tid;
                    int row = idx >> 5, c4 = idx & 31;
                    cpa16(ku + (row * KP + c4 * 4) * 4,
                          K + (size_t)(n0n + row) * Hdim + c4 * 4);
                    cpa16(vu + (row * VP + c4 * 4) * 4,
                          V + (size_t)(n0n + row) * Hdim + c4 * 4);
                }
                cpa_commit();
            }

            const float* Kc = Kb[cur];
            const float* Vc = Vb[cur];
            const int n0 = 32 * (2 * i + h);

            // S = Q . K^T  (16 rows x 32 cols per warp)
            float sacc[4][4];
            #pragma unroll
            for (int nb = 0; nb < 4; nb++)
                #pragma unroll
                for (int c = 0; c < 4; c++) sacc[nb][c] = 0.f;

            #pragma unroll
            for (int ks = 0; ks < 16; ks++) {
                const int k = ks * 8;
                uint32_t qa[4];
                qa[0] = __float_as_uint(Qs[(r0q    ) * QP + k + tg    ]);
                qa[1] = __float_as_uint(Qs[(r0q + 8) * QP + k + tg    ]);
                qa[2] = __float_as_uint(Qs[(r0q    ) * QP + k + tg + 4]);
                qa[3] = __float_as_uint(Qs[(r0q + 8) * QP + k + tg + 4]);
                #pragma unroll
                for (int nb = 0; nb < 4; nb++) {
                    uint32_t b0 = __float_as_uint(Kc[(nb * 8 + g) * KP + k + tg    ]);
                    uint32_t b1 = __float_as_uint(Kc[(nb * 8 + g) * KP + k + tg + 4]);
                    mma_tf32(sacc[nb], qa, b0, b1);
                }
            }

            // Causal mask (only last tile of this half touches the diagonal).
            if (i == qt) {
                const int row0 = m0 + r0q;
                const int row1 = row0 + 8;
                #pragma unroll
                for (int nb = 0; nb < 4; nb++) {
                    int c0 = n0 + nb * 8 + 2 * tg;
                    if (c0     > row0) sacc[nb][0] = -1e30f;
                    if (c0 + 1 > row0) sacc[nb][1] = -1e30f;
                    if (c0     > row1) sacc[nb][2] = -1e30f;
                    if (c0 + 1 > row1) sacc[nb][3] = -1e30f;
                }
            }

            // Online softmax (rows r0q, r0q+8), quad reduction.
            float mx0 = -1e30f, mx1 = -1e30f;
            #pragma unroll
            for (int nb = 0; nb < 4; nb++) {
                mx0 = fmaxf(mx0, fmaxf(sacc[nb][0], sacc[nb][1]));
                mx1 = fmaxf(mx1, fmaxf(sacc[nb][2], sacc[nb][3]));
            }
            mx0 = fmaxf(mx0, __shfl_xor_sync(0xffffffffu, mx0, 1));
            mx0 = fmaxf(mx0, __shfl_xor_sync(0xffffffffu, mx0, 2));
            mx1 = fmaxf(mx1, __shfl_xor_sync(0xffffffffu, mx1, 1));
            mx1 = fmaxf(mx1, __shfl_xor_sync(0xffffffffu, mx1, 2));

            float mn0 = fmaxf(mrow0, mx0), mn1 = fmaxf(mrow1, mx1);
            float corr0 = __expf(mrow0 - mn0), corr1 = __expf(mrow1 - mn1);
            float rs0 = 0.f, rs1 = 0.f;
            #pragma unroll
            for (int nb = 0; nb < 4; nb++) {
                float p00 = cvt_tf32f(__expf(sacc[nb][0] - mn0));
                float p01 = cvt_tf32f(__expf(sacc[nb][1] - mn0));
                float p10 = cvt_tf32f(__expf(sacc[nb][2] - mn1));
                float p11 = cvt_tf32f(__expf(sacc[nb][3] - mn1));
                rs0 += p00 + p01;
                rs1 += p10 + p11;
                float2 lo = {p00, p01}, hi = {p10, p11};
                *(float2*)&Ps[(r0q    ) * PP + nb * 8 + 2 * tg] = lo;
                *(float2*)&Ps[(r0q + 8) * PP + nb * 8 + 2 * tg] = hi;
            }
            rs0 += __shfl_xor_sync(0xffffffffu, rs0, 1);
            rs0 += __shfl_xor_sync(0xffffffffu, rs0, 2);
            rs1 += __shfl_xor_sync(0xffffffffu, rs1, 1);
            rs1 += __shfl_xor_sync(0xffffffffu, rs1, 2);
            lrow0 = lrow0 * corr0 + rs0;
            lrow1 = lrow1 * corr1 + rs1;
            mrow0 = mn0; mrow1 = mn1;
            #pragma unroll
            for (int nb = 0; nb < 16; nb++) {
                of[nb][0] *= corr0; of[nb][1] *= corr0;
                of[nb][2] *= corr1; of[nb][3] *= corr1;
            }
            __syncwarp();

            // O += P . V  (16 x 128 per warp, k = 32)
            #pragma unroll
            for (int ks = 0; ks < 4; ks++) {
                const int k = ks * 8;
                uint32_t pa[4];
                pa[0] = __float_as_uint(Ps[(r0q    ) * PP + k + tg    ]);
                pa[1] = __float_as_uint(Ps[(r0q + 8) * PP + k + tg    ]);
                pa[2] = __float_as_uint(Ps[(r0q    ) * PP + k + tg + 4]);
                pa[3] = __float_as_uint(Ps[(r0q + 8) * PP + k + tg + 4]);
                #pragma unroll
                for (int nb = 0; nb < 16; nb++) {
                    uint32_t b0 = __float_as_uint(Vc[(k + tg    ) * VP + nb * 8 + g]);
                    uint32_t b1 = __float_as_uint(Vc[(k + tg + 4) * VP + nb * 8 + g]);
                    mma_tf32(of[nb], pa, b0, b1);
                }
            }
        }

        // Store unnormalized partials + (m, l).
        const size_t obase = (size_t)h * BT * Hdim;
        const int grow = b * Tdim + m0 + r0q;
        #pragma unroll
        for (int nb = 0; nb < 16; nb++) {
            float2 lo = {of[nb][0], of[nb][1]};
            float2 hi = {of[nb][2], of[nb][3]};
            *(float2*)(g_Op + obase + (size_t)(grow    ) * Hdim + nb * 8 + 2 * tg) = lo;
            *(float2*)(g_Op + obase + (size_t)(grow + 8) * Hdim + nb * 8 + 2 * tg) = hi;
        }
        if (tg == 0) {
            g_m[h * BT + grow    ] = mrow0;
            g_l[h * BT + grow    ] = lrow0;
            g_m[h * BT + grow + 8] = mrow1;
            g_l[h * BT + grow + 8] = lrow1;
        }
    }
}

// ---------------------------------------------------------------------------
// Kernel 3: combine the two split-KV halves.
// grid = 2048, block = 256: one float4 per thread.
// ---------------------------------------------------------------------------
__global__ __launch_bounds__(256) void combine_kernel(float* __restrict__ out)
{
    const int idx = blockIdx.x * 256 + threadIdx.x;   // 0 .. 524287
    const int row = idx >> 5;
    const int c4  = idx & 31;

    const float m0 = g_m[row], m1 = g_m[BT + row];
    const float l0 = g_l[row], l1 = g_l[BT + row];
    const float m  = fmaxf(m0, m1);
    const float c0 = __expf(m0 - m);
    const float c1 = __expf(m1 - m);
    const float inv = 1.f / (c0 * l0 + c1 * l1);

    const float4 a = *(const float4*)(g_Op + (size_t)row * Hdim + c4 * 4);
    const float4 bb = *(const float4*)(g_Op + (size_t)BT * Hdim
                                       + (size_t)row * Hdim + c4 * 4);
    float4 r;
    r.x = (c0 * a.x + c1 * bb.x) * inv;
    r.y = (c0 * a.y + c1 * bb.y) * inv;
    r.z = (c0 * a.z + c1 * bb.z) * inv;
    r.w = (c0 * a.w + c1 * bb.w) * inv;
    *(float4*)(out + (size_t)row * Hdim + c4 * 4) = r;
}

// ---------------------------------------------------------------------------
extern "C" void kernel_launch(void* const* d_in, const int* in_sizes, int n_in,
                              void* d_out, int out_size)
{
    const float* x  = (const float*)d_in[0];
    const float* Wq = (const float*)d_in[1];
    const float* Wk = (const float*)d_in[2];
    const float* Wv = (const float*)d_in[3];
    float* out = (float*)d_out;

    const int qkv_smem = (2 * 128 * APAD + 2 * 32 * BROW) * (int)sizeof(float); // 138240
    cudaFuncSetAttribute(qkv_kernel,
                         cudaFuncAttributeMaxDynamicSharedMemorySize, qkv_smem);
    qkv_kernel<<<BT / 128, 384, qkv_smem>>>(x, Wq, Wk, Wv);

    const int attn_smem = (64*QP + 2*32*KP + 2*32*VP + 64*PP) * (int)sizeof(float); // 110592
    cudaFuncSetAttribute(attn_kernel,
                         cudaFuncAttributeMaxDynamicSharedMemorySize, attn_smem);
    attn_kernel<<<dim3(32, Bdim), 128, attn_smem>>>();

    combine_kernel<<<(BT * Hdim / 4) / 256, 256>>>(out);
}

// round 6
// speedup vs baseline: 1.0599x; 1.0599x over previous
#include <cuda_runtime.h>
#include <cstdint>

#define Bdim 8
#define Tdim 2048
#define Cdim 1024
#define Hdim 128
#define BT (Bdim*Tdim)

// Scratch (device globals, allocation-free).
__device__ float g_Q[BT * Hdim];       // pre-scaled, tf32-rounded
__device__ float g_K[BT * Hdim];       // tf32-rounded
__device__ float g_V[BT * Hdim];       // tf32-rounded
__device__ float g_Op[2 * BT * Hdim];  // unnormalized partial O per half
__device__ float g_m[2 * BT];
__device__ float g_l[2 * BT];

// ---------------------------------------------------------------------------
// Helpers
// ---------------------------------------------------------------------------
__device__ __forceinline__ uint32_t cvt_tf32(float x) {
    uint32_t u;
    asm("cvt.rna.tf32.f32 %0, %1;" : "=r"(u) : "f"(x));
    return u;
}
__device__ __forceinline__ float cvt_tf32f(float x) {
    return __uint_as_float(cvt_tf32(x));
}
__device__ __forceinline__ void mma_tf32(float* d, const uint32_t* a,
                                         uint32_t b0, uint32_t b1) {
    asm volatile(
        "mma.sync.aligned.m16n8k8.row.col.f32.tf32.tf32.f32 "
        "{%0,%1,%2,%3}, {%4,%5,%6,%7}, {%8,%9}, {%0,%1,%2,%3};"
        : "+f"(d[0]), "+f"(d[1]), "+f"(d[2]), "+f"(d[3])
        : "r"(a[0]), "r"(a[1]), "r"(a[2]), "r"(a[3]), "r"(b0), "r"(b1));
}
__device__ __forceinline__ uint32_t s2u(const void* p) {
    return (uint32_t)__cvta_generic_to_shared(p);
}
__device__ __forceinline__ void cpa16(uint32_t dst, const void* src) {
    asm volatile("cp.async.cg.shared.global [%0], [%1], 16;" :: "r"(dst), "l"(src));
}
__device__ __forceinline__ void cpa_commit() {
    asm volatile("cp.async.commit_group;");
}
__device__ __forceinline__ void cpa_wait0() {
    asm volatile("cp.async.wait_group 0;");
}

// ---------------------------------------------------------------------------
// Kernel 1: fused QKV projection, TF32 mma.sync, cp.async double-buffered.
// grid = (BT/128, 3), block = 128 (4 warps), 3 CTAs/SM -> single wave.
// CTA tile 128x128, warp 32x128. Stores tf32-rounded (Q pre-scaled).
// ---------------------------------------------------------------------------
#define AS_PAD 36
#define BS_PAD 136

__global__ __launch_bounds__(128, 3) void qkv_kernel(
    const float* __restrict__ x, const float* __restrict__ Wq,
    const float* __restrict__ Wk, const float* __restrict__ Wv)
{
    extern __shared__ float sm[];
    float* As[2] = { sm,                sm + 128 * AS_PAD };
    float* Bs[2] = { sm + 2*128*AS_PAD, sm + 2*128*AS_PAD + 32 * BS_PAD };

    const int m0 = blockIdx.x * 128;
    const float* W;
    float* outp;
    float osc;
    if (blockIdx.y == 0)      { W = Wq; outp = g_Q; osc = 0.08838834764831845f; }
    else if (blockIdx.y == 1) { W = Wk; outp = g_K; osc = 1.f; }
    else                      { W = Wv; outp = g_V; osc = 1.f; }

    const int tid  = threadIdx.x;
    const int wid  = tid >> 5;
    const int lane = tid & 31;
    const int g    = lane >> 2;
    const int tg   = lane & 3;

    const int arow = tid >> 3, ac4 = tid & 7;
    const int brow = tid >> 5, bc4 = tid & 31;

    // Stage chunk 0.
    {
        uint32_t au = s2u(As[0]), bu = s2u(Bs[0]);
        #pragma unroll
        for (int tt = 0; tt < 8; tt++) {
            int row = arow + tt * 16;
            cpa16(au + (row * AS_PAD + ac4 * 4) * 4,
                  x + (size_t)(m0 + row) * Cdim + ac4 * 4);
        }
        #pragma unroll
        for (int tt = 0; tt < 8; tt++) {
            int row = brow + tt * 4;
            cpa16(bu + (row * BS_PAD + bc4 * 4) * 4,
                  W + (size_t)row * Hdim + bc4 * 4);
        }
        cpa_commit();
    }

    float oc[2][16][4];
    #pragma unroll
    for (int mb = 0; mb < 2; mb++)
        #pragma unroll
        for (int nb = 0; nb < 16; nb++)
            #pragma unroll
            for (int c = 0; c < 4; c++) oc[mb][nb][c] = 0.f;

    #pragma unroll 1
    for (int kc = 0; kc < 32; kc++) {
        cpa_wait0();
        __syncthreads();
        const int cur = kc & 1;
        if (kc + 1 < 32) {
            const int nxt = cur ^ 1;
            uint32_t au = s2u(As[nxt]), bu = s2u(Bs[nxt]);
            const int k0 = (kc + 1) * 32;
            #pragma unroll
            for (int tt = 0; tt < 8; tt++) {
                int row = arow + tt * 16;
                cpa16(au + (row * AS_PAD + ac4 * 4) * 4,
                      x + (size_t)(m0 + row) * Cdim + k0 + ac4 * 4);
            }
            #pragma unroll
            for (int tt = 0; tt < 8; tt++) {
                int row = brow + tt * 4;
                cpa16(bu + (row * BS_PAD + bc4 * 4) * 4,
                      W + (size_t)(k0 + row) * Hdim + bc4 * 4);
            }
            cpa_commit();
        }

        const float* A = As[cur];
        const float* B = Bs[cur];
        #pragma unroll
        for (int ks = 0; ks < 4; ks++) {
            const int k = ks * 8;
            const int r0 = wid * 32 + g;
            uint32_t a0[4], a1[4];
            a0[0] = cvt_tf32(A[(r0     ) * AS_PAD + k + tg    ]);
            a0[1] = cvt_tf32(A[(r0 +  8) * AS_PAD + k + tg    ]);
            a0[2] = cvt_tf32(A[(r0     ) * AS_PAD + k + tg + 4]);
            a0[3] = cvt_tf32(A[(r0 +  8) * AS_PAD + k + tg + 4]);
            a1[0] = cvt_tf32(A[(r0 + 16) * AS_PAD + k + tg    ]);
            a1[1] = cvt_tf32(A[(r0 + 24) * AS_PAD + k + tg    ]);
            a1[2] = cvt_tf32(A[(r0 + 16) * AS_PAD + k + tg + 4]);
            a1[3] = cvt_tf32(A[(r0 + 24) * AS_PAD + k + tg + 4]);
            #pragma unroll
            for (int nb = 0; nb < 16; nb++) {
                uint32_t b0 = cvt_tf32(B[(k + tg    ) * BS_PAD + nb * 8 + g]);
                uint32_t b1 = cvt_tf32(B[(k + tg + 4) * BS_PAD + nb * 8 + g]);
                mma_tf32(oc[0][nb], a0, b0, b1);
                mma_tf32(oc[1][nb], a1, b0, b1);
            }
        }
    }

    #pragma unroll
    for (int mb = 0; mb < 2; mb++) {
        int r0 = m0 + wid * 32 + mb * 16 + g;
        #pragma unroll
        for (int nb = 0; nb < 16; nb++) {
            float2 lo = {cvt_tf32f(oc[mb][nb][0] * osc), cvt_tf32f(oc[mb][nb][1] * osc)};
            float2 hi = {cvt_tf32f(oc[mb][nb][2] * osc), cvt_tf32f(oc[mb][nb][3] * osc)};
            *(float2*)(outp + (size_t)(r0    ) * Hdim + nb * 8 + 2 * tg) = lo;
            *(float2*)(outp + (size_t)(r0 + 8) * Hdim + nb * 8 + 2 * tg) = hi;
        }
    }
}

// ---------------------------------------------------------------------------
// Kernel 2: causal flash attention, split-KV (2 halves) + q-tile pairing,
// TF32 mma.sync, Q fragments held in registers.
// grid (32, 8): blockIdx.x = pair*2 + half; 33 uniform 32-wide kv steps/CTA.
// block = 128 (4 warps), 110.6 KB smem -> 2 CTAs/SM, single wave.
// ---------------------------------------------------------------------------
#define QP 132
#define KP 132
#define VP 132
#define PP 36

__global__ __launch_bounds__(128) void attn_kernel()
{
    extern __shared__ float smem[];
    float* Qs    = smem;                            // [64][132]
    float* Kb[2] = { smem +  8448, smem + 12672 };  // [32][132] x2
    float* Vb[2] = { smem + 16896, smem + 21120 };  // [32][132] x2
    float* Ps    = smem + 25344;                    // [64][36]

    const int p = (int)blockIdx.x >> 1;
    const int h = (int)blockIdx.x & 1;
    const int b = blockIdx.y;
    const int tid  = threadIdx.x;
    const int wid  = tid >> 5;
    const int lane = tid & 31;
    const int g    = lane >> 2;
    const int tg   = lane & 3;
    const int r0q  = wid * 16 + g;

    const float* Q = g_Q + (size_t)b * Tdim * Hdim;
    const float* K = g_K + (size_t)b * Tdim * Hdim;
    const float* V = g_V + (size_t)b * Tdim * Hdim;

    #pragma unroll 1
    for (int phase = 0; phase < 2; phase++) {
        const int qt = phase == 0 ? p : 31 - p;
        const int m0 = qt * 64;

        __syncthreads();

        // Stage Q (64x128) + first K/V tile (32x128 each).
        {
            uint32_t qu = s2u(Qs);
            #pragma unroll
            for (int tt = 0; tt < 16; tt++) {
                int idx = tt * 128 + tid;
                int row = idx >> 5, c4 = idx & 31;
                cpa16(qu + (row * QP + c4 * 4) * 4,
                      Q + (size_t)(m0 + row) * Hdim + c4 * 4);
            }
            const int n0 = 32 * h;
            uint32_t ku = s2u(Kb[0]), vu = s2u(Vb[0]);
            #pragma unroll
            for (int tt = 0; tt < 8; tt++) {
                int idx = tt * 128 + tid;
                int row = idx >> 5, c4 = idx & 31;
                cpa16(ku + (row * KP + c4 * 4) * 4,
                      K + (size_t)(n0 + row) * Hdim + c4 * 4);
                cpa16(vu + (row * VP + c4 * 4) * 4,
                      V + (size_t)(n0 + row) * Hdim + c4 * 4);
            }
            cpa_commit();
        }

        float of[16][4];
        #pragma unroll
        for (int nb = 0; nb < 16; nb++)
            #pragma unroll
            for (int c = 0; c < 4; c++) of[nb][c] = 0.f;
        float mrow0 = -1e30f, mrow1 = -1e30f, lrow0 = 0.f, lrow1 = 0.f;
        uint32_t qf[16][4];

        #pragma unroll 1
        for (int i = 0; i <= qt; i++) {
            const int cur = i & 1;
            cpa_wait0();
            __syncthreads();

            if (i == 0) {
                #pragma unroll
                for (int ks = 0; ks < 16; ks++) {
                    const int k = ks * 8;
                    qf[ks][0] = __float_as_uint(Qs[(r0q    ) * QP + k + tg    ]);
                    qf[ks][1] = __float_as_uint(Qs[(r0q + 8) * QP + k + tg    ]);
                    qf[ks][2] = __float_as_uint(Qs[(r0q    ) * QP + k + tg + 4]);
                    qf[ks][3] = __float_as_uint(Qs[(r0q + 8) * QP + k + tg + 4]);
                }
            }

            if (i < qt) {
                const int n0n = 32 * (2 * (i + 1) + h);
                uint32_t ku = s2u(Kb[cur ^ 1]), vu = s2u(Vb[cur ^ 1]);
                #pragma unroll
                for (int tt = 0; tt < 8; tt++) {
                    int idx = tt * 128 + tid;
                    int row = idx >> 5, c4 = idx & 31;
                    cpa16(ku + (row * KP + c4 * 4) * 4,
                          K + (size_t)(n0n + row) * Hdim + c4 * 4);
                    cpa16(vu + (row * VP + c4 * 4) * 4,
                          V + (size_t)(n0n + row) * Hdim + c4 * 4);
                }
                cpa_commit();
            }

            const float* Kc = Kb[cur];
            const float* Vc = Vb[cur];
            const int n0 = 32 * (2 * i + h);

            float sacc[4][4];
            #pragma unroll
            for (int nb = 0; nb < 4; nb++)
                #pragma unroll
                for (int c = 0; c < 4; c++) sacc[nb][c] = 0.f;

            #pragma unroll
            for (int ks = 0; ks < 16; ks++) {
                const int k = ks * 8;
                #pragma unroll
                for (int nb = 0; nb < 4; nb++) {
                    uint32_t b0 = __float_as_uint(Kc[(nb * 8 + g) * KP + k + tg    ]);
                    uint32_t b1 = __float_as_uint(Kc[(nb * 8 + g) * KP + k + tg + 4]);
                    mma_tf32(sacc[nb], qf[ks], b0, b1);
                }
            }

            if (i == qt) {
                const int row0 = m0 + r0q;
                const int row1 = row0 + 8;
                #pragma unroll
                for (int nb = 0; nb < 4; nb++) {
                    int c0 = n0 + nb * 8 + 2 * tg;
                    if (c0     > row0) sacc[nb][0] = -1e30f;
                    if (c0 + 1 > row0) sacc[nb][1] = -1e30f;
                    if (c0     > row1) sacc[nb][2] = -1e30f;
                    if (c0 + 1 > row1) sacc[nb][3] = -1e30f;
                }
            }

            float mx0 = -1e30f, mx1 = -1e30f;
            #pragma unroll
            for (int nb = 0; nb < 4; nb++) {
                mx0 = fmaxf(mx0, fmaxf(sacc[nb][0], sacc[nb][1]));
                mx1 = fmaxf(mx1, fmaxf(sacc[nb][2], sacc[nb][3]));
            }
            mx0 = fmaxf(mx0, __shfl_xor_sync(0xffffffffu, mx0, 1));
            mx0 = fmaxf(mx0, __shfl_xor_sync(0xffffffffu, mx0, 2));
            mx1 = fmaxf(mx1, __shfl_xor_sync(0xffffffffu, mx1, 1));
            mx1 = fmaxf(mx1, __shfl_xor_sync(0xffffffffu, mx1, 2));

            float mn0 = fmaxf(mrow0, mx0), mn1 = fmaxf(mrow1, mx1);
            float corr0 = __expf(mrow0 - mn0), corr1 = __expf(mrow1 - mn1);
            float rs0 = 0.f, rs1 = 0.f;
            #pragma unroll
            for (int nb = 0; nb < 4; nb++) {
                float p00 = cvt_tf32f(__expf(sacc[nb][0] - mn0));
                float p01 = cvt_tf32f(__expf(sacc[nb][1] - mn0));
                float p10 = cvt_tf32f(__expf(sacc[nb][2] - mn1));
                float p11 = cvt_tf32f(__expf(sacc[nb][3] - mn1));
                rs0 += p00 + p01;
                rs1 += p10 + p11;
                float2 lo = {p00, p01}, hi = {p10, p11};
                *(float2*)&Ps[(r0q    ) * PP + nb * 8 + 2 * tg] = lo;
                *(float2*)&Ps[(r0q + 8) * PP + nb * 8 + 2 * tg] = hi;
            }
            rs0 += __shfl_xor_sync(0xffffffffu, rs0, 1);
            rs0 += __shfl_xor_sync(0xffffffffu, rs0, 2);
            rs1 += __shfl_xor_sync(0xffffffffu, rs1, 1);
            rs1 += __shfl_xor_sync(0xffffffffu, rs1, 2);
            lrow0 = lrow0 * corr0 + rs0;
            lrow1 = lrow1 * corr1 + rs1;
            mrow0 = mn0; mrow1 = mn1;
            #pragma unroll
            for (int nb = 0; nb < 16; nb++) {
                of[nb][0] *= corr0; of[nb][1] *= corr0;
                of[nb][2] *= corr1; of[nb][3] *= corr1;
            }
            __syncwarp();

            #pragma unroll
            for (int ks = 0; ks < 4; ks++) {
                const int k = ks * 8;
                uint32_t pa[4];
                pa[0] = __float_as_uint(Ps[(r0q    ) * PP + k + tg    ]);
                pa[1] = __float_as_uint(Ps[(r0q + 8) * PP + k + tg    ]);
                pa[2] = __float_as_uint(Ps[(r0q    ) * PP + k + tg + 4]);
                pa[3] = __float_as_uint(Ps[(r0q + 8) * PP + k + tg + 4]);
                #pragma unroll
                for (int nb = 0; nb < 16; nb++) {
                    uint32_t b0 = __float_as_uint(Vc[(k + tg    ) * VP + nb * 8 + g]);
                    uint32_t b1 = __float_as_uint(Vc[(k + tg + 4) * VP + nb * 8 + g]);
                    mma_tf32(of[nb], pa, b0, b1);
                }
            }
        }

        const size_t obase = (size_t)h * BT * Hdim;
        const int grow = b * Tdim + m0 + r0q;
        #pragma unroll
        for (int nb = 0; nb < 16; nb++) {
            float2 lo = {of[nb][0], of[nb][1]};
            float2 hi = {of[nb][2], of[nb][3]};
            *(float2*)(g_Op + obase + (size_t)(grow    ) * Hdim + nb * 8 + 2 * tg) = lo;
            *(float2*)(g_Op + obase + (size_t)(grow + 8) * Hdim + nb * 8 + 2 * tg) = hi;
        }
        if (tg == 0) {
            g_m[h * BT + grow    ] = mrow0;
            g_l[h * BT + grow    ] = lrow0;
            g_m[h * BT + grow + 8] = mrow1;
            g_l[h * BT + grow + 8] = lrow1;
        }
    }
}

// ---------------------------------------------------------------------------
// Kernel 3: combine the two split-KV halves.
// ---------------------------------------------------------------------------
__global__ __launch_bounds__(256) void combine_kernel(float* __restrict__ out)
{
    const int idx = blockIdx.x * 256 + threadIdx.x;
    const int row = idx >> 5;
    const int c4  = idx & 31;

    const float m0 = g_m[row], m1 = g_m[BT + row];
    const float l0 = g_l[row], l1 = g_l[BT + row];
    const float m  = fmaxf(m0, m1);
    const float c0 = __expf(m0 - m);
    const float c1 = __expf(m1 - m);
    const float inv = 1.f / (c0 * l0 + c1 * l1);

    const float4 a = *(const float4*)(g_Op + (size_t)row * Hdim + c4 * 4);
    const float4 bb = *(const float4*)(g_Op + (size_t)BT * Hdim
                                       + (size_t)row * Hdim + c4 * 4);
    float4 r;
    r.x = (c0 * a.x + c1 * bb.x) * inv;
    r.y = (c0 * a.y + c1 * bb.y) * inv;
    r.z = (c0 * a.z + c1 * bb.z) * inv;
    r.w = (c0 * a.w + c1 * bb.w) * inv;
    *(float4*)(out + (size_t)row * Hdim + c4 * 4) = r;
}

// ---------------------------------------------------------------------------
extern "C" void kernel_launch(void* const* d_in, const int* in_sizes, int n_in,
                              void* d_out, int out_size)
{
    const float* x  = (const float*)d_in[0];
    const float* Wq = (const float*)d_in[1];
    const float* Wk = (const float*)d_in[2];
    const float* Wv = (const float*)d_in[3];
    float* out = (float*)d_out;

    const int qkv_smem = (2 * 128 * AS_PAD + 2 * 32 * BS_PAD) * (int)sizeof(float); // 71680
    cudaFuncSetAttribute(qkv_kernel,
                         cudaFuncAttributeMaxDynamicSharedMemorySize, qkv_smem);
    qkv_kernel<<<dim3(BT / 128, 3), 128, qkv_smem>>>(x, Wq, Wk, Wv);

    const int attn_smem = (64*QP + 2*32*KP + 2*32*VP + 64*PP) * (int)sizeof(float); // 110592
    cudaFuncSetAttribute(attn_kernel,
                         cudaFuncAttributeMaxDynamicSharedMemorySize, attn_smem);
    attn_kernel<<<dim3(32, Bdim), 128, attn_smem>>>();

    combine_kernel<<<(BT * Hdim / 4) / 256, 256>>>(out);
}